// round 14
// baseline (speedup 1.0000x reference)
#include <cuda_runtime.h>
#include <cuda_fp16.h>
#include <cstdint>
#include <cstddef>

typedef unsigned long long u64;
typedef unsigned int u32;

#define TT    512
#define BB    2
#define CC    256
#define TPR   12
#define HID   32
#define INNER 256
#define NQKV  768
#define BN_EPS 1e-5f
#define SCALE  0.0625f

// ---------------- scratch (no allocs allowed) ----------------
__device__ __align__(16) u64   g_w1p[16 * TPR];
__device__ __align__(16) u64   g_b1p[16];
__device__ __align__(16) u32   g_w2ph[16 * CC];   // fp16x2 layer-2 weights
__device__ __align__(16) float g_b2f[CC];
// xb as fp16 hi/lo A-fragment words: [row][ks(16)][tig(4)][half(2)]
__device__ __align__(16) u32   g_xbh[BB * TT * 128];
__device__ __align__(16) u32   g_xbl[BB * TT * 128];
// w_qkv fragment-native: per (n, ks): 4 tig groups of uint4 {bh(p), bh(p+4), bl(p), bl(p+4)}
__device__ __align__(16) u32   g_wq2[NQKV * 16 * 16];
// q: [row][ks(16)][tig(4)][{h(p), h(p+4), l(p), l(p+4)}]
__device__ __align__(16) u32   g_q2[BB * TT * 256];
// k: hi-only: [row][ks(16)][tig(4)][{h(p), h(p+4)}]
__device__ __align__(16) u32   g_k2[BB * TT * 128];
// v transposed hi-only: [b][ksj(32)][d(256)][tigj(4)][{h(j 2tigj,2tigj+1), h(+8,+9)}]
__device__ __align__(16) u32   g_vt2[BB * 32 * 256 * 8];

// ---------------- helpers ----------------
__device__ __forceinline__ u64 pk2(float x, float y) {
    u64 r; asm("mov.b64 %0, {%1,%2};" : "=l"(r) : "f"(x), "f"(y)); return r;
}
__device__ __forceinline__ void upk2(u64 v, float &x, float &y) {
    asm("mov.b64 {%0,%1}, %2;" : "=f"(x), "=f"(y) : "l"(v));
}
__device__ __forceinline__ u64 fma2(u64 a, u64 b, u64 c) {
    u64 d; asm("fma.rn.f32x2 %0, %1, %2, %3;" : "=l"(d) : "l"(a), "l"(b), "l"(c)); return d;
}
__device__ __forceinline__ u32 h2pk(float lo, float hi) {
    __half2 t = __floats2half2_rn(lo, hi);
    return *(u32*)&t;
}
__device__ __forceinline__ float2 h2f2(u32 w) {
    __half2 t = *(__half2*)&w;
    return __half22float2(t);
}
__device__ __forceinline__ u32 s2u(const void* p) {
    u32 a; asm("{ .reg .u64 t; cvta.to.shared.u64 t, %1; cvt.u32.u64 %0, t; }" : "=r"(a) : "l"(p));
    return a;
}
__device__ __forceinline__ void mma16816h(float &d0, float &d1, float &d2, float &d3,
                                          u32 a0, u32 a1, u32 a2, u32 a3,
                                          u32 b0, u32 b1) {
    asm volatile("mma.sync.aligned.m16n8k16.row.col.f32.f16.f16.f32 "
                 "{%0,%1,%2,%3}, {%4,%5,%6,%7}, {%8,%9}, {%0,%1,%2,%3};"
                 : "+f"(d0), "+f"(d1), "+f"(d2), "+f"(d3)
                 : "r"(a0), "r"(a1), "r"(a2), "r"(a3), "r"(b0), "r"(b1));
}
__device__ __forceinline__ void ldsm4(u32 &r0, u32 &r1, u32 &r2, u32 &r3, u32 addr) {
    asm volatile("ldmatrix.sync.aligned.m8n8.x4.shared.b16 {%0,%1,%2,%3}, [%4];"
                 : "=r"(r0), "=r"(r1), "=r"(r2), "=r"(r3) : "r"(addr));
}

// ---------------- prep: fold (block 192) + w_qkv convert (blocks 0-191) ----------------
__global__ void prep_kernel(const float* __restrict__ w1, const float* __restrict__ b1,
                            const float* __restrict__ g1, const float* __restrict__ be1,
                            const float* __restrict__ m1, const float* __restrict__ v1,
                            const float* __restrict__ w2, const float* __restrict__ b2,
                            const float* __restrict__ g2, const float* __restrict__ be2,
                            const float* __restrict__ m2, const float* __restrict__ v2,
                            const float* __restrict__ wqkv)
{
    if (blockIdx.x < 192) {
        int n = (blockIdx.x % 3) * 256 + threadIdx.x;
        int byy = blockIdx.x / 3;
        int ks = byy >> 2, tig = byy & 3;
        int k0 = (ks * 8 + tig) * 2;
        float w0 = wqkv[(size_t)k0 * NQKV + n];
        float w1v = wqkv[(size_t)(k0 + 1) * NQKV + n];
        float w8 = wqkv[(size_t)(k0 + 8) * NQKV + n];
        float w9 = wqkv[(size_t)(k0 + 9) * NQKV + n];
        u32 bh0 = h2pk(w0, w1v), bh1 = h2pk(w8, w9);
        float2 r0 = h2f2(bh0), r1 = h2f2(bh1);
        u32 bl0 = h2pk(w0 - r0.x, w1v - r0.y);
        u32 bl1 = h2pk(w8 - r1.x, w9 - r1.y);
        *(uint4*)(g_wq2 + ((size_t)(n * 16 + ks) * 4 + tig) * 4) = make_uint4(bh0, bh1, bl0, bl1);
        return;
    }
    __shared__ float a1s[HID], b1s[HID];
    int t = threadIdx.x;
    if (t < HID) {
        float a = g1[t] * rsqrtf(v1[t] + BN_EPS);
        a1s[t] = a;
        b1s[t] = (b1[t] - m1[t]) * a + be1[t];
    }
    __syncthreads();
    if (t < 16) {
        for (int d = 0; d < TPR; d++)
            g_w1p[t * TPR + d] = pk2(w1[d * HID + 2 * t]     * a1s[2 * t],
                                     w1[d * HID + 2 * t + 1] * a1s[2 * t + 1]);
        g_b1p[t] = pk2(b1s[2 * t], b1s[2 * t + 1]);
    }
    int c = t;
    float a2 = g2[c] * rsqrtf(v2[c] + BN_EPS);
    g_b2f[c] = (b2[c] - m2[c]) * a2 + be2[c];
    for (int kp = 0; kp < 16; kp++) {
        float w0  = w2[(2 * kp)     * CC + c] * a2;
        float w1v = w2[(2 * kp + 1) * CC + c] * a2;
        g_w2ph[kp * CC + c] = h2pk(w0, w1v);
    }
}

// ---------------- TPR-MLP: hi-only fp16 h1 + ldmatrix + pipelined ----------------
#define H1S 80
#define BIAS_SMEM (2 * 256 * H1S + 208 * 8)

__device__ __forceinline__ void layer1_kp(char* buf, int tid, int kp,
                                          const u64* rp, const u64* w1s)
{
    u64 acc = w1s[192 + kp];
    #pragma unroll
    for (int d = 0; d < 12; d++) acc = fma2(rp[d], w1s[kp * TPR + d], acc);
    float h0, h1; upk2(acc, h0, h1);
    h0 = fmaxf(h0, 0.f); h1 = fmaxf(h1, 0.f);
    ((u32*)(buf + tid * H1S))[kp] = h2pk(h0, h1);
}

__global__ __launch_bounds__(256, 2) void bias_kernel(const float* __restrict__ x,
                                                      const float* __restrict__ r)
{
    extern __shared__ char smem[];
    char* buf0 = smem;
    char* buf1 = smem + 256 * H1S;
    u64*  w1s  = (u64*)(smem + 2 * 256 * H1S);

    int tid  = threadIdx.x;
    int bi   = blockIdx.x;
    int warp = tid >> 5, lane = tid & 31;
    int gid  = lane >> 2, tig = lane & 3;

    if (tid < 208) w1s[tid] = (tid < 192) ? g_w1p[tid] : g_b1p[tid - 192];

    u32 bh[4][2][2];
    #pragma unroll
    for (int nt = 0; nt < 4; nt++) {
        int c = warp * 32 + nt * 8 + gid;
        #pragma unroll
        for (int ks = 0; ks < 2; ks++) {
            bh[nt][ks][0] = g_w2ph[(ks * 8 + tig)     * CC + c];
            bh[nt][ks][1] = g_w2ph[(ks * 8 + tig + 4) * CC + c];
        }
    }

    const float4* rr0 = (const float4*)(r + (size_t)bi * (TT * TPR) + (size_t)tid * TPR);
    const float4* rr1 = rr0 + 768;
    float4 A0 = rr0[0], B0 = rr0[1], C0 = rr0[2];
    float4 A1 = rr1[0], B1 = rr1[1], C1 = rr1[2];

    int t4 = lane >> 3;
    u32 laneoff = (u32)(((t4 & 1) * 8 + (lane & 7)) * H1S + (t4 >> 1) * 16);
    u32 h1b0 = s2u(buf0) + laneoff;
    u32 h1b1 = s2u(buf1) + laneoff;

    float m0[4], m1[4];
    #pragma unroll
    for (int nt = 0; nt < 4; nt++) { m0[nt] = -3.4e38f; m1[nt] = -3.4e38f; }

    __syncthreads();

    u64 rp[12];
    rp[0]=pk2(A0.x,A0.x); rp[1]=pk2(A0.y,A0.y); rp[2]=pk2(A0.z,A0.z); rp[3]=pk2(A0.w,A0.w);
    rp[4]=pk2(B0.x,B0.x); rp[5]=pk2(B0.y,B0.y); rp[6]=pk2(B0.z,B0.z); rp[7]=pk2(B0.w,B0.w);
    rp[8]=pk2(C0.x,C0.x); rp[9]=pk2(C0.y,C0.y); rp[10]=pk2(C0.z,C0.z); rp[11]=pk2(C0.w,C0.w);

    #pragma unroll 4
    for (int kp = 0; kp < 16; kp++) layer1_kp(buf0, tid, kp, rp, w1s);

    rp[0]=pk2(A1.x,A1.x); rp[1]=pk2(A1.y,A1.y); rp[2]=pk2(A1.z,A1.z); rp[3]=pk2(A1.w,A1.w);
    rp[4]=pk2(B1.x,B1.x); rp[5]=pk2(B1.y,B1.y); rp[6]=pk2(B1.z,B1.z); rp[7]=pk2(B1.w,B1.w);
    rp[8]=pk2(C1.x,C1.x); rp[9]=pk2(C1.y,C1.y); rp[10]=pk2(C1.z,C1.z); rp[11]=pk2(C1.w,C1.w);

    __syncthreads();

    #pragma unroll 2
    for (int jt = 0; jt < 16; jt++) {
        u32 a = h1b0 + (u32)jt * (16 * H1S);
        u32 ah0[4], ah1[4];
        ldsm4(ah0[0],ah0[1],ah0[2],ah0[3], a);
        ldsm4(ah1[0],ah1[1],ah1[2],ah1[3], a + 32);
        #pragma unroll
        for (int nt = 0; nt < 4; nt++) {
            float d0 = 0.f, d1 = 0.f, d2 = 0.f, d3 = 0.f;
            mma16816h(d0,d1,d2,d3, ah0[0],ah0[1],ah0[2],ah0[3], bh[nt][0][0], bh[nt][0][1]);
            mma16816h(d0,d1,d2,d3, ah1[0],ah1[1],ah1[2],ah1[3], bh[nt][1][0], bh[nt][1][1]);
            m0[nt] = fmaxf(m0[nt], fmaxf(d0, d2));
            m1[nt] = fmaxf(m1[nt], fmaxf(d1, d3));
        }
        layer1_kp(buf1, tid, jt, rp, w1s);
    }
    __syncthreads();

    #pragma unroll 2
    for (int jt = 0; jt < 16; jt++) {
        u32 a = h1b1 + (u32)jt * (16 * H1S);
        u32 ah0[4], ah1[4];
        ldsm4(ah0[0],ah0[1],ah0[2],ah0[3], a);
        ldsm4(ah1[0],ah1[1],ah1[2],ah1[3], a + 32);
        #pragma unroll
        for (int nt = 0; nt < 4; nt++) {
            float d0 = 0.f, d1 = 0.f, d2 = 0.f, d3 = 0.f;
            mma16816h(d0,d1,d2,d3, ah0[0],ah0[1],ah0[2],ah0[3], bh[nt][0][0], bh[nt][0][1]);
            mma16816h(d0,d1,d2,d3, ah1[0],ah1[1],ah1[2],ah1[3], bh[nt][1][0], bh[nt][1][1]);
            m0[nt] = fmaxf(m0[nt], fmaxf(d0, d2));
            m1[nt] = fmaxf(m1[nt], fmaxf(d1, d3));
        }
    }

    #pragma unroll
    for (int nt = 0; nt < 4; nt++) {
        #pragma unroll
        for (int o = 4; o < 32; o <<= 1) {
            m0[nt] = fmaxf(m0[nt], __shfl_xor_sync(0xffffffffu, m0[nt], o));
            m1[nt] = fmaxf(m1[nt], __shfl_xor_sync(0xffffffffu, m1[nt], o));
        }
        if (gid == 0) {
            int c0 = warp * 32 + nt * 8 + tig * 2;
            float v0 = x[(size_t)bi * CC + c0]     + fmaxf(m0[nt] + g_b2f[c0],     0.f);
            float v1 = x[(size_t)bi * CC + c0 + 1] + fmaxf(m1[nt] + g_b2f[c0 + 1], 0.f);
            int P = c0 >> 1;
            int word = (P & ~7) + ((P & 3) << 1) + ((P >> 2) & 1);
            u32 hi = h2pk(v0, v1);
            float2 bk = h2f2(hi);
            g_xbh[bi * 128 + word] = hi;
            g_xbl[bi * 128 + word] = h2pk(v0 - bk.x, v1 - bk.y);
        }
    }
}

// ---------------- qkv via fp16 MMA (3-term), k-split across warp pairs ----------
__global__ __launch_bounds__(256) void qkv_mma_kernel()
{
    __shared__ float sacc[4][8][32][4];
    int tid = threadIdx.x;
    int warp = tid >> 5, lane = tid & 31, gid = lane >> 2, tig = lane & 3;
    int rt = warp & 3, kh = warp >> 2;
    int r0 = blockIdx.y * 64 + rt * 16;
    int n0 = blockIdx.x * 64;
    int type = blockIdx.x >> 2;

    const u32* ah = g_xbh + (size_t)(r0 + gid) * 128 + kh * 64 + tig * 2;
    const u32* al = g_xbl + (size_t)(r0 + gid) * 128 + kh * 64 + tig * 2;

    float acc[8][4] = {};
    #pragma unroll 4
    for (int ks = 0; ks < 8; ks++) {
        uint2 Ah0 = *(const uint2*)(ah + ks * 8);
        uint2 Ah1 = *(const uint2*)(ah + 8 * 128 + ks * 8);
        uint2 Al0 = *(const uint2*)(al + ks * 8);
        uint2 Al1 = *(const uint2*)(al + 8 * 128 + ks * 8);
        #pragma unroll
        for (int nt = 0; nt < 8; nt++) {
            int n = n0 + nt * 8 + gid;
            uint4 B = *(const uint4*)(g_wq2 + ((size_t)(n * 16 + kh * 8 + ks) * 4 + tig) * 4);
            mma16816h(acc[nt][0],acc[nt][1],acc[nt][2],acc[nt][3],
                      Ah0.x, Ah1.x, Ah0.y, Ah1.y, B.x, B.y);
            mma16816h(acc[nt][0],acc[nt][1],acc[nt][2],acc[nt][3],
                      Ah0.x, Ah1.x, Ah0.y, Ah1.y, B.z, B.w);
            mma16816h(acc[nt][0],acc[nt][1],acc[nt][2],acc[nt][3],
                      Al0.x, Al1.x, Al0.y, Al1.y, B.x, B.y);
        }
    }

    if (kh == 0) {
        #pragma unroll
        for (int nt = 0; nt < 8; nt++)
            *(float4*)&sacc[rt][nt][lane][0] = make_float4(acc[nt][0], acc[nt][1], acc[nt][2], acc[nt][3]);
    }
    __syncthreads();
    if (kh == 0) return;

    #pragma unroll
    for (int nt = 0; nt < 8; nt++) {
        float4 t = *(float4*)&sacc[rt][nt][lane][0];
        acc[nt][0] += t.x; acc[nt][1] += t.y; acc[nt][2] += t.z; acc[nt][3] += t.w;
    }

    if (type == 0) {
        #pragma unroll
        for (int nt = 0; nt < 8; nt++) {
            int P = (n0 >> 1) + nt * 4 + tig;
            int word = ((P >> 3) << 4) + ((P & 3) << 2) + ((P >> 2) & 1);
            u32* q0 = g_q2 + (size_t)(r0 + gid) * 256 + word;
            u32* q1 = g_q2 + (size_t)(r0 + gid + 8) * 256 + word;
            u32 h0 = h2pk(acc[nt][0], acc[nt][1]); float2 b0 = h2f2(h0);
            u32 h1 = h2pk(acc[nt][2], acc[nt][3]); float2 b1 = h2f2(h1);
            q0[0] = h0; q0[2] = h2pk(acc[nt][0] - b0.x, acc[nt][1] - b0.y);
            q1[0] = h1; q1[2] = h2pk(acc[nt][2] - b1.x, acc[nt][3] - b1.y);
        }
    } else if (type == 1) {
        #pragma unroll
        for (int nt = 0; nt < 8; nt++) {
            int P = ((n0 - 256) >> 1) + nt * 4 + tig;
            int word = (P & ~7) + ((P & 3) << 1) + ((P >> 2) & 1);
            g_k2[(size_t)(r0 + gid) * 128 + word]     = h2pk(acc[nt][0], acc[nt][1]);
            g_k2[(size_t)(r0 + gid + 8) * 128 + word] = h2pk(acc[nt][2], acc[nt][3]);
        }
    } else {
        int bb = r0 >> 9, ksj = (r0 & 511) >> 4;
        #pragma unroll
        for (int nt = 0; nt < 8; nt++) {
            float p0 = __shfl_xor_sync(0xffffffffu, acc[nt][0], 4);
            float p1 = __shfl_xor_sync(0xffffffffu, acc[nt][1], 4);
            float p2 = __shfl_xor_sync(0xffffffffu, acc[nt][2], 4);
            float p3 = __shfl_xor_sync(0xffffffffu, acc[nt][3], 4);
            if (!(gid & 1)) {
                int tigj = gid >> 1;
                int d0c = n0 - 512 + nt * 8 + 2 * tig;
                u32* v0p = g_vt2 + ((size_t)(bb * 32 + ksj) * 256 + d0c) * 8 + tigj * 2;
                v0p[0] = h2pk(acc[nt][0], p0);
                v0p[1] = h2pk(acc[nt][2], p2);
                u32* v1p = v0p + 8;
                v1p[0] = h2pk(acc[nt][1], p1);
                v1p[1] = h2pk(acc[nt][3], p3);
            }
        }
    }
}

// ---------------- fused attention: 512 threads, 16 warps ----------------
#define QSTR 260
#define SSTR 520
#define PSTR 260
#define ATT_SMEM (16*QSTR*4 + 16*SSTR*4 + 2*16*PSTR*4)

__global__ __launch_bounds__(512, 1) void attn_kernel(float* __restrict__ out)
{
    extern __shared__ char smem[];
    u32*   sq  = (u32*)smem;
    float* ssc = (float*)(smem + 16 * QSTR * 4);
    u32*   sph = (u32*)(smem + 16 * QSTR * 4 + 16 * SSTR * 4);
    u32*   spl = sph + 16 * PSTR;

    int tid = threadIdx.x;
    int w = tid >> 5, lane = tid & 31, gid = lane >> 2, tig = lane & 3;
    int b  = blockIdx.x >> 5;
    int i0 = (blockIdx.x & 31) * 16;

    // stage Q tile: 16 rows x 256 words, 8 words per thread
    {
        int i = tid >> 5, c0 = (tid & 31) * 8;
        const uint4* src = (const uint4*)(g_q2 + (size_t)(b * TT + i0 + i) * 256 + c0);
        uint4* dst = (uint4*)(sq + i * QSTR + c0);
        dst[0] = src[0]; dst[1] = src[1];
    }
    __syncthreads();

    // phase 1: S = QK^T, warp w covers j in [w*32, w*32+32)
    float accs[4][4] = {};
    {
        const u32* qr0 = sq + gid * QSTR;
        const u32* qr1 = sq + (gid + 8) * QSTR;
        const u32* kbase = g_k2 + (size_t)(b * TT + w * 32 + gid) * 128 + tig * 2;
        #pragma unroll 4
        for (int ks = 0; ks < 16; ks++) {
            uint4 A0 = *(const uint4*)(qr0 + ks * 16 + tig * 4);
            uint4 A1 = *(const uint4*)(qr1 + ks * 16 + tig * 4);
            #pragma unroll
            for (int nt = 0; nt < 4; nt++) {
                uint2 B = *(const uint2*)(kbase + (size_t)nt * 8 * 128 + ks * 8);
                mma16816h(accs[nt][0],accs[nt][1],accs[nt][2],accs[nt][3],
                          A0.x, A1.x, A0.y, A1.y, B.x, B.y);
                mma16816h(accs[nt][0],accs[nt][1],accs[nt][2],accs[nt][3],
                          A0.z, A1.z, A0.w, A1.w, B.x, B.y);
            }
        }
        #pragma unroll
        for (int nt = 0; nt < 4; nt++) {
            int col = w * 32 + nt * 8 + 2 * tig;
            *(float2*)&ssc[gid * SSTR + col]       = make_float2(accs[nt][0] * SCALE, accs[nt][1] * SCALE);
            *(float2*)&ssc[(gid + 8) * SSTR + col] = make_float2(accs[nt][2] * SCALE, accs[nt][3] * SCALE);
        }
    }
    __syncthreads();

    // softmax: warp w handles row w
    {
        int rrow = w;
        float sv[16];
        float mx = -3.4e38f;
        #pragma unroll
        for (int q = 0; q < 16; q++) {
            sv[q] = ssc[rrow * SSTR + q * 32 + lane];
            mx = fmaxf(mx, sv[q]);
        }
        #pragma unroll
        for (int o = 16; o; o >>= 1) mx = fmaxf(mx, __shfl_xor_sync(0xffffffffu, mx, o));
        float sum = 0.f;
        #pragma unroll
        for (int q = 0; q < 16; q++) { sv[q] = __expf(sv[q] - mx); sum += sv[q]; }
        #pragma unroll
        for (int o = 16; o; o >>= 1) sum += __shfl_xor_sync(0xffffffffu, sum, o);
        float inv = 1.f / sum;
        #pragma unroll
        for (int q = 0; q < 16; q++) {
            float p = sv[q] * inv;
            float pr = __shfl_xor_sync(0xffffffffu, p, 1);
            if (!(lane & 1)) {
                u32 ph = h2pk(p, pr);
                float2 bk = h2f2(ph);
                u32 pl = h2pk(p - bk.x, pr - bk.y);
                int jp = q * 16 + (lane >> 1);
                sph[rrow * PSTR + jp] = ph;
                spl[rrow * PSTR + jp] = pl;
            }
        }
    }
    __syncthreads();

    // phase 2: O = P V, warp w covers d in [w*16, w*16+16)
    float acco[2][4] = {};
    {
        const u32* vbase = g_vt2 + ((size_t)b * 32 * 256 + (size_t)(w * 16 + gid)) * 8 + tig * 2;
        #pragma unroll 4
        for (int ks = 0; ks < 32; ks++) {
            int c0 = ks * 8 + tig;
            u32 a0h = sph[gid * PSTR + c0],       a1h = sph[(gid + 8) * PSTR + c0];
            u32 a2h = sph[gid * PSTR + c0 + 4],   a3h = sph[(gid + 8) * PSTR + c0 + 4];
            u32 a0l = spl[gid * PSTR + c0],       a1l = spl[(gid + 8) * PSTR + c0];
            u32 a2l = spl[gid * PSTR + c0 + 4],   a3l = spl[(gid + 8) * PSTR + c0 + 4];
            #pragma unroll
            for (int nt = 0; nt < 2; nt++) {
                uint2 B = *(const uint2*)(vbase + ((size_t)ks * 256 + nt * 8) * 8);
                mma16816h(acco[nt][0],acco[nt][1],acco[nt][2],acco[nt][3],
                          a0h, a1h, a2h, a3h, B.x, B.y);
                mma16816h(acco[nt][0],acco[nt][1],acco[nt][2],acco[nt][3],
                          a0l, a1l, a2l, a3l, B.x, B.y);
            }
        }
    }
    #pragma unroll
    for (int nt = 0; nt < 2; nt++) {
        int col = w * 16 + nt * 8 + 2 * tig;
        *(float2*)&out[(size_t)(b * TT + i0 + gid) * CC + col]     = make_float2(acco[nt][0], acco[nt][1]);
        *(float2*)&out[(size_t)(b * TT + i0 + gid + 8) * CC + col] = make_float2(acco[nt][2], acco[nt][3]);
    }
}

// ---------------- launch ----------------
extern "C" void kernel_launch(void* const* d_in, const int* in_sizes, int n_in,
                              void* d_out, int out_size)
{
    (void)in_sizes; (void)n_in; (void)out_size;
    const float* x    = (const float*)d_in[0];
    const float* r    = (const float*)d_in[1];
    const float* w1   = (const float*)d_in[2];
    const float* b1   = (const float*)d_in[3];
    const float* g1   = (const float*)d_in[4];
    const float* be1  = (const float*)d_in[5];
    const float* m1   = (const float*)d_in[6];
    const float* v1   = (const float*)d_in[7];
    const float* w2   = (const float*)d_in[8];
    const float* b2   = (const float*)d_in[9];
    const float* g2   = (const float*)d_in[10];
    const float* be2  = (const float*)d_in[11];
    const float* m2   = (const float*)d_in[12];
    const float* v2   = (const float*)d_in[13];
    const float* wqkv = (const float*)d_in[14];
    float* out = (float*)d_out;

    cudaFuncSetAttribute(bias_kernel, cudaFuncAttributeMaxDynamicSharedMemorySize, BIAS_SMEM);
    cudaFuncSetAttribute(attn_kernel, cudaFuncAttributeMaxDynamicSharedMemorySize, ATT_SMEM);

    prep_kernel<<<193, 256>>>(w1, b1, g1, be1, m1, v1, w2, b2, g2, be2, m2, v2, wqkv);
    bias_kernel<<<BB * TT, 256, BIAS_SMEM>>>(x, r);
    qkv_mma_kernel<<<dim3(12, 16), 256>>>();
    attn_kernel<<<BB * 32, 512, ATT_SMEM>>>(out);
}

// round 15
// speedup vs baseline: 1.0649x; 1.0649x over previous
#include <cuda_runtime.h>
#include <cuda_fp16.h>
#include <cstdint>
#include <cstddef>

typedef unsigned long long u64;
typedef unsigned int u32;

#define TT    512
#define BB    2
#define CC    256
#define TPR   12
#define HID   32
#define INNER 256
#define NQKV  768
#define BN_EPS 1e-5f
#define SCALE  0.0625f

// ---------------- scratch (no allocs allowed) ----------------
__device__ __align__(16) u64   g_w1p[16 * TPR];
__device__ __align__(16) u64   g_b1p[16];
__device__ __align__(16) u32   g_w2ph[16 * CC];
__device__ __align__(16) float g_b2f[CC];
__device__ __align__(16) u32   g_xbh[BB * TT * 128];
__device__ __align__(16) u32   g_xbl[BB * TT * 128];
__device__ __align__(16) u32   g_wq2[NQKV * 16 * 16];
__device__ __align__(16) u32   g_q2[BB * TT * 256];
__device__ __align__(16) u32   g_k2[BB * TT * 128];
__device__ __align__(16) u32   g_vt2[BB * 32 * 256 * 8];
// flash-split partials: [split(2)][row(1024)]
__device__ __align__(16) float g_po[2 * BB * TT * CC];   // 2 MB unnormalized O
__device__ float g_pm[2 * BB * TT];
__device__ float g_pl[2 * BB * TT];

// ---------------- helpers ----------------
__device__ __forceinline__ u64 pk2(float x, float y) {
    u64 r; asm("mov.b64 %0, {%1,%2};" : "=l"(r) : "f"(x), "f"(y)); return r;
}
__device__ __forceinline__ void upk2(u64 v, float &x, float &y) {
    asm("mov.b64 {%0,%1}, %2;" : "=f"(x), "=f"(y) : "l"(v));
}
__device__ __forceinline__ u64 fma2(u64 a, u64 b, u64 c) {
    u64 d; asm("fma.rn.f32x2 %0, %1, %2, %3;" : "=l"(d) : "l"(a), "l"(b), "l"(c)); return d;
}
__device__ __forceinline__ u32 h2pk(float lo, float hi) {
    __half2 t = __floats2half2_rn(lo, hi);
    return *(u32*)&t;
}
__device__ __forceinline__ float2 h2f2(u32 w) {
    __half2 t = *(__half2*)&w;
    return __half22float2(t);
}
__device__ __forceinline__ u32 s2u(const void* p) {
    u32 a; asm("{ .reg .u64 t; cvta.to.shared.u64 t, %1; cvt.u32.u64 %0, t; }" : "=r"(a) : "l"(p));
    return a;
}
__device__ __forceinline__ void mma16816h(float &d0, float &d1, float &d2, float &d3,
                                          u32 a0, u32 a1, u32 a2, u32 a3,
                                          u32 b0, u32 b1) {
    asm volatile("mma.sync.aligned.m16n8k16.row.col.f32.f16.f16.f32 "
                 "{%0,%1,%2,%3}, {%4,%5,%6,%7}, {%8,%9}, {%0,%1,%2,%3};"
                 : "+f"(d0), "+f"(d1), "+f"(d2), "+f"(d3)
                 : "r"(a0), "r"(a1), "r"(a2), "r"(a3), "r"(b0), "r"(b1));
}
__device__ __forceinline__ void ldsm4(u32 &r0, u32 &r1, u32 &r2, u32 &r3, u32 addr) {
    asm volatile("ldmatrix.sync.aligned.m8n8.x4.shared.b16 {%0,%1,%2,%3}, [%4];"
                 : "=r"(r0), "=r"(r1), "=r"(r2), "=r"(r3) : "r"(addr));
}

// ---------------- prep: fold (block 192) + w_qkv convert (blocks 0-191) ----------------
__global__ void prep_kernel(const float* __restrict__ w1, const float* __restrict__ b1,
                            const float* __restrict__ g1, const float* __restrict__ be1,
                            const float* __restrict__ m1, const float* __restrict__ v1,
                            const float* __restrict__ w2, const float* __restrict__ b2,
                            const float* __restrict__ g2, const float* __restrict__ be2,
                            const float* __restrict__ m2, const float* __restrict__ v2,
                            const float* __restrict__ wqkv)
{
    if (blockIdx.x < 192) {
        int n = (blockIdx.x % 3) * 256 + threadIdx.x;
        int byy = blockIdx.x / 3;
        int ks = byy >> 2, tig = byy & 3;
        int k0 = (ks * 8 + tig) * 2;
        float w0 = wqkv[(size_t)k0 * NQKV + n];
        float w1v = wqkv[(size_t)(k0 + 1) * NQKV + n];
        float w8 = wqkv[(size_t)(k0 + 8) * NQKV + n];
        float w9 = wqkv[(size_t)(k0 + 9) * NQKV + n];
        u32 bh0 = h2pk(w0, w1v), bh1 = h2pk(w8, w9);
        float2 r0 = h2f2(bh0), r1 = h2f2(bh1);
        u32 bl0 = h2pk(w0 - r0.x, w1v - r0.y);
        u32 bl1 = h2pk(w8 - r1.x, w9 - r1.y);
        *(uint4*)(g_wq2 + ((size_t)(n * 16 + ks) * 4 + tig) * 4) = make_uint4(bh0, bh1, bl0, bl1);
        return;
    }
    __shared__ float a1s[HID], b1s[HID];
    int t = threadIdx.x;
    if (t < HID) {
        float a = g1[t] * rsqrtf(v1[t] + BN_EPS);
        a1s[t] = a;
        b1s[t] = (b1[t] - m1[t]) * a + be1[t];
    }
    __syncthreads();
    if (t < 16) {
        for (int d = 0; d < TPR; d++)
            g_w1p[t * TPR + d] = pk2(w1[d * HID + 2 * t]     * a1s[2 * t],
                                     w1[d * HID + 2 * t + 1] * a1s[2 * t + 1]);
        g_b1p[t] = pk2(b1s[2 * t], b1s[2 * t + 1]);
    }
    int c = t;
    float a2 = g2[c] * rsqrtf(v2[c] + BN_EPS);
    g_b2f[c] = (b2[c] - m2[c]) * a2 + be2[c];
    for (int kp = 0; kp < 16; kp++) {
        float w0  = w2[(2 * kp)     * CC + c] * a2;
        float w1v = w2[(2 * kp + 1) * CC + c] * a2;
        g_w2ph[kp * CC + c] = h2pk(w0, w1v);
    }
}

// ---------------- TPR-MLP: hi-only fp16 h1 + ldmatrix + pipelined ----------------
#define H1S 80
#define BIAS_SMEM (2 * 256 * H1S + 208 * 8)

__device__ __forceinline__ void layer1_kp(char* buf, int tid, int kp,
                                          const u64* rp, const u64* w1s)
{
    u64 acc = w1s[192 + kp];
    #pragma unroll
    for (int d = 0; d < 12; d++) acc = fma2(rp[d], w1s[kp * TPR + d], acc);
    float h0, h1; upk2(acc, h0, h1);
    h0 = fmaxf(h0, 0.f); h1 = fmaxf(h1, 0.f);
    ((u32*)(buf + tid * H1S))[kp] = h2pk(h0, h1);
}

__global__ __launch_bounds__(256, 2) void bias_kernel(const float* __restrict__ x,
                                                      const float* __restrict__ r)
{
    extern __shared__ char smem[];
    char* buf0 = smem;
    char* buf1 = smem + 256 * H1S;
    u64*  w1s  = (u64*)(smem + 2 * 256 * H1S);

    int tid  = threadIdx.x;
    int bi   = blockIdx.x;
    int warp = tid >> 5, lane = tid & 31;
    int gid  = lane >> 2, tig = lane & 3;

    if (tid < 208) w1s[tid] = (tid < 192) ? g_w1p[tid] : g_b1p[tid - 192];

    u32 bh[4][2][2];
    #pragma unroll
    for (int nt = 0; nt < 4; nt++) {
        int c = warp * 32 + nt * 8 + gid;
        #pragma unroll
        for (int ks = 0; ks < 2; ks++) {
            bh[nt][ks][0] = g_w2ph[(ks * 8 + tig)     * CC + c];
            bh[nt][ks][1] = g_w2ph[(ks * 8 + tig + 4) * CC + c];
        }
    }

    const float4* rr0 = (const float4*)(r + (size_t)bi * (TT * TPR) + (size_t)tid * TPR);
    const float4* rr1 = rr0 + 768;
    float4 A0 = rr0[0], B0 = rr0[1], C0 = rr0[2];
    float4 A1 = rr1[0], B1 = rr1[1], C1 = rr1[2];

    int t4 = lane >> 3;
    u32 laneoff = (u32)(((t4 & 1) * 8 + (lane & 7)) * H1S + (t4 >> 1) * 16);
    u32 h1b0 = s2u(buf0) + laneoff;
    u32 h1b1 = s2u(buf1) + laneoff;

    float m0[4], m1[4];
    #pragma unroll
    for (int nt = 0; nt < 4; nt++) { m0[nt] = -3.4e38f; m1[nt] = -3.4e38f; }

    __syncthreads();

    u64 rp[12];
    rp[0]=pk2(A0.x,A0.x); rp[1]=pk2(A0.y,A0.y); rp[2]=pk2(A0.z,A0.z); rp[3]=pk2(A0.w,A0.w);
    rp[4]=pk2(B0.x,B0.x); rp[5]=pk2(B0.y,B0.y); rp[6]=pk2(B0.z,B0.z); rp[7]=pk2(B0.w,B0.w);
    rp[8]=pk2(C0.x,C0.x); rp[9]=pk2(C0.y,C0.y); rp[10]=pk2(C0.z,C0.z); rp[11]=pk2(C0.w,C0.w);

    #pragma unroll 4
    for (int kp = 0; kp < 16; kp++) layer1_kp(buf0, tid, kp, rp, w1s);

    rp[0]=pk2(A1.x,A1.x); rp[1]=pk2(A1.y,A1.y); rp[2]=pk2(A1.z,A1.z); rp[3]=pk2(A1.w,A1.w);
    rp[4]=pk2(B1.x,B1.x); rp[5]=pk2(B1.y,B1.y); rp[6]=pk2(B1.z,B1.z); rp[7]=pk2(B1.w,B1.w);
    rp[8]=pk2(C1.x,C1.x); rp[9]=pk2(C1.y,C1.y); rp[10]=pk2(C1.z,C1.z); rp[11]=pk2(C1.w,C1.w);

    __syncthreads();

    #pragma unroll 2
    for (int jt = 0; jt < 16; jt++) {
        u32 a = h1b0 + (u32)jt * (16 * H1S);
        u32 ah0[4], ah1[4];
        ldsm4(ah0[0],ah0[1],ah0[2],ah0[3], a);
        ldsm4(ah1[0],ah1[1],ah1[2],ah1[3], a + 32);
        #pragma unroll
        for (int nt = 0; nt < 4; nt++) {
            float d0 = 0.f, d1 = 0.f, d2 = 0.f, d3 = 0.f;
            mma16816h(d0,d1,d2,d3, ah0[0],ah0[1],ah0[2],ah0[3], bh[nt][0][0], bh[nt][0][1]);
            mma16816h(d0,d1,d2,d3, ah1[0],ah1[1],ah1[2],ah1[3], bh[nt][1][0], bh[nt][1][1]);
            m0[nt] = fmaxf(m0[nt], fmaxf(d0, d2));
            m1[nt] = fmaxf(m1[nt], fmaxf(d1, d3));
        }
        layer1_kp(buf1, tid, jt, rp, w1s);
    }
    __syncthreads();

    #pragma unroll 2
    for (int jt = 0; jt < 16; jt++) {
        u32 a = h1b1 + (u32)jt * (16 * H1S);
        u32 ah0[4], ah1[4];
        ldsm4(ah0[0],ah0[1],ah0[2],ah0[3], a);
        ldsm4(ah1[0],ah1[1],ah1[2],ah1[3], a + 32);
        #pragma unroll
        for (int nt = 0; nt < 4; nt++) {
            float d0 = 0.f, d1 = 0.f, d2 = 0.f, d3 = 0.f;
            mma16816h(d0,d1,d2,d3, ah0[0],ah0[1],ah0[2],ah0[3], bh[nt][0][0], bh[nt][0][1]);
            mma16816h(d0,d1,d2,d3, ah1[0],ah1[1],ah1[2],ah1[3], bh[nt][1][0], bh[nt][1][1]);
            m0[nt] = fmaxf(m0[nt], fmaxf(d0, d2));
            m1[nt] = fmaxf(m1[nt], fmaxf(d1, d3));
        }
    }

    #pragma unroll
    for (int nt = 0; nt < 4; nt++) {
        #pragma unroll
        for (int o = 4; o < 32; o <<= 1) {
            m0[nt] = fmaxf(m0[nt], __shfl_xor_sync(0xffffffffu, m0[nt], o));
            m1[nt] = fmaxf(m1[nt], __shfl_xor_sync(0xffffffffu, m1[nt], o));
        }
        if (gid == 0) {
            int c0 = warp * 32 + nt * 8 + tig * 2;
            float v0 = x[(size_t)bi * CC + c0]     + fmaxf(m0[nt] + g_b2f[c0],     0.f);
            float v1 = x[(size_t)bi * CC + c0 + 1] + fmaxf(m1[nt] + g_b2f[c0 + 1], 0.f);
            int P = c0 >> 1;
            int word = (P & ~7) + ((P & 3) << 1) + ((P >> 2) & 1);
            u32 hi = h2pk(v0, v1);
            float2 bk = h2f2(hi);
            g_xbh[bi * 128 + word] = hi;
            g_xbl[bi * 128 + word] = h2pk(v0 - bk.x, v1 - bk.y);
        }
    }
}

// ---------------- qkv via fp16 MMA (3-term), n-tile 32, k-split ----------
// grid (24, 16), block 256 (8 warps): warp = (rowtile 0-3, khalf 0-1).
__global__ __launch_bounds__(256) void qkv_mma_kernel()
{
    __shared__ float sacc[4][4][32][4];   // 8 KB partial sums from khalf 0
    int tid = threadIdx.x;
    int warp = tid >> 5, lane = tid & 31, gid = lane >> 2, tig = lane & 3;
    int rt = warp & 3, kh = warp >> 2;
    int r0 = blockIdx.y * 64 + rt * 16;
    int n0 = blockIdx.x * 32;
    int type = blockIdx.x >> 3;

    const u32* ah = g_xbh + (size_t)(r0 + gid) * 128 + kh * 64 + tig * 2;
    const u32* al = g_xbl + (size_t)(r0 + gid) * 128 + kh * 64 + tig * 2;

    float acc[4][4] = {};
    #pragma unroll 4
    for (int ks = 0; ks < 8; ks++) {
        uint2 Ah0 = *(const uint2*)(ah + ks * 8);
        uint2 Ah1 = *(const uint2*)(ah + 8 * 128 + ks * 8);
        uint2 Al0 = *(const uint2*)(al + ks * 8);
        uint2 Al1 = *(const uint2*)(al + 8 * 128 + ks * 8);
        #pragma unroll
        for (int nt = 0; nt < 4; nt++) {
            int n = n0 + nt * 8 + gid;
            uint4 B = *(const uint4*)(g_wq2 + ((size_t)(n * 16 + kh * 8 + ks) * 4 + tig) * 4);
            mma16816h(acc[nt][0],acc[nt][1],acc[nt][2],acc[nt][3],
                      Ah0.x, Ah1.x, Ah0.y, Ah1.y, B.x, B.y);
            mma16816h(acc[nt][0],acc[nt][1],acc[nt][2],acc[nt][3],
                      Ah0.x, Ah1.x, Ah0.y, Ah1.y, B.z, B.w);
            mma16816h(acc[nt][0],acc[nt][1],acc[nt][2],acc[nt][3],
                      Al0.x, Al1.x, Al0.y, Al1.y, B.x, B.y);
        }
    }

    if (kh == 0) {
        #pragma unroll
        for (int nt = 0; nt < 4; nt++)
            *(float4*)&sacc[rt][nt][lane][0] = make_float4(acc[nt][0], acc[nt][1], acc[nt][2], acc[nt][3]);
    }
    __syncthreads();
    if (kh == 0) return;

    #pragma unroll
    for (int nt = 0; nt < 4; nt++) {
        float4 t = *(float4*)&sacc[rt][nt][lane][0];
        acc[nt][0] += t.x; acc[nt][1] += t.y; acc[nt][2] += t.z; acc[nt][3] += t.w;
    }

    if (type == 0) {
        #pragma unroll
        for (int nt = 0; nt < 4; nt++) {
            int P = (n0 >> 1) + nt * 4 + tig;
            int word = ((P >> 3) << 4) + ((P & 3) << 2) + ((P >> 2) & 1);
            u32* q0 = g_q2 + (size_t)(r0 + gid) * 256 + word;
            u32* q1 = g_q2 + (size_t)(r0 + gid + 8) * 256 + word;
            u32 h0 = h2pk(acc[nt][0], acc[nt][1]); float2 b0 = h2f2(h0);
            u32 h1 = h2pk(acc[nt][2], acc[nt][3]); float2 b1 = h2f2(h1);
            q0[0] = h0; q0[2] = h2pk(acc[nt][0] - b0.x, acc[nt][1] - b0.y);
            q1[0] = h1; q1[2] = h2pk(acc[nt][2] - b1.x, acc[nt][3] - b1.y);
        }
    } else if (type == 1) {
        #pragma unroll
        for (int nt = 0; nt < 4; nt++) {
            int P = ((n0 - 256) >> 1) + nt * 4 + tig;
            int word = (P & ~7) + ((P & 3) << 1) + ((P >> 2) & 1);
            g_k2[(size_t)(r0 + gid) * 128 + word]     = h2pk(acc[nt][0], acc[nt][1]);
            g_k2[(size_t)(r0 + gid + 8) * 128 + word] = h2pk(acc[nt][2], acc[nt][3]);
        }
    } else {
        int bb = r0 >> 9, ksj = (r0 & 511) >> 4;
        #pragma unroll
        for (int nt = 0; nt < 4; nt++) {
            float p0 = __shfl_xor_sync(0xffffffffu, acc[nt][0], 4);
            float p1 = __shfl_xor_sync(0xffffffffu, acc[nt][1], 4);
            float p2 = __shfl_xor_sync(0xffffffffu, acc[nt][2], 4);
            float p3 = __shfl_xor_sync(0xffffffffu, acc[nt][3], 4);
            if (!(gid & 1)) {
                int tigj = gid >> 1;
                int d0c = n0 - 512 + nt * 8 + 2 * tig;
                u32* v0p = g_vt2 + ((size_t)(bb * 32 + ksj) * 256 + d0c) * 8 + tigj * 2;
                v0p[0] = h2pk(acc[nt][0], p0);
                v0p[1] = h2pk(acc[nt][2], p2);
                u32* v1p = v0p + 8;
                v1p[0] = h2pk(acc[nt][1], p1);
                v1p[1] = h2pk(acc[nt][3], p3);
            }
        }
    }
}

// ---------------- flash-split attention: j-halves across 2 blocks ----------------
#define QSTR 260
#define SSTR 260
#define PSTR 132
#define ATT_SMEM (16*QSTR*4 + 16*SSTR*4 + 2*16*PSTR*4)

__global__ __launch_bounds__(512, 1) void attn_kernel()
{
    extern __shared__ char smem[];
    u32*   sq  = (u32*)smem;                                   // [16][260]
    float* ssc = (float*)(smem + 16 * QSTR * 4);               // [16][260] (256 used)
    u32*   sph = (u32*)(smem + 16 * QSTR * 4 + 16 * SSTR * 4); // [16][132]
    u32*   spl = sph + 16 * PSTR;

    int tid = threadIdx.x;
    int w = tid >> 5, lane = tid & 31, gid = lane >> 2, tig = lane & 3;
    int b  = blockIdx.x >> 6;
    int it = (blockIdx.x >> 1) & 31;
    int jh = blockIdx.x & 1;
    int i0 = it * 16;

    // stage Q tile
    {
        int i = tid >> 5, c0 = (tid & 31) * 8;
        const uint4* src = (const uint4*)(g_q2 + (size_t)(b * TT + i0 + i) * 256 + c0);
        uint4* dst = (uint4*)(sq + i * QSTR + c0);
        dst[0] = src[0]; dst[1] = src[1];
    }
    __syncthreads();

    // phase 1: S over j-local [w*16, w*16+16) of this j-half
    float accs[2][4] = {};
    {
        const u32* qr0 = sq + gid * QSTR;
        const u32* qr1 = sq + (gid + 8) * QSTR;
        const u32* kbase = g_k2 + (size_t)(b * TT + jh * 256 + w * 16 + gid) * 128 + tig * 2;
        #pragma unroll 4
        for (int ks = 0; ks < 16; ks++) {
            uint4 A0 = *(const uint4*)(qr0 + ks * 16 + tig * 4);
            uint4 A1 = *(const uint4*)(qr1 + ks * 16 + tig * 4);
            #pragma unroll
            for (int nt = 0; nt < 2; nt++) {
                uint2 B = *(const uint2*)(kbase + (size_t)nt * 8 * 128 + ks * 8);
                mma16816h(accs[nt][0],accs[nt][1],accs[nt][2],accs[nt][3],
                          A0.x, A1.x, A0.y, A1.y, B.x, B.y);
                mma16816h(accs[nt][0],accs[nt][1],accs[nt][2],accs[nt][3],
                          A0.z, A1.z, A0.w, A1.w, B.x, B.y);
            }
        }
        #pragma unroll
        for (int nt = 0; nt < 2; nt++) {
            int col = w * 16 + nt * 8 + 2 * tig;
            *(float2*)&ssc[gid * SSTR + col]       = make_float2(accs[nt][0] * SCALE, accs[nt][1] * SCALE);
            *(float2*)&ssc[(gid + 8) * SSTR + col] = make_float2(accs[nt][2] * SCALE, accs[nt][3] * SCALE);
        }
    }
    __syncthreads();

    // partial softmax: warp w handles row w over 256 local cols
    {
        int rrow = w;
        float sv[8];
        float mx = -3.4e38f;
        #pragma unroll
        for (int q = 0; q < 8; q++) {
            sv[q] = ssc[rrow * SSTR + q * 32 + lane];
            mx = fmaxf(mx, sv[q]);
        }
        #pragma unroll
        for (int o = 16; o; o >>= 1) mx = fmaxf(mx, __shfl_xor_sync(0xffffffffu, mx, o));
        float sum = 0.f;
        #pragma unroll
        for (int q = 0; q < 8; q++) { sv[q] = __expf(sv[q] - mx); sum += sv[q]; }
        #pragma unroll
        for (int o = 16; o; o >>= 1) sum += __shfl_xor_sync(0xffffffffu, sum, o);
        if (lane == 0) {
            int rg = b * TT + i0 + rrow;
            g_pm[jh * (BB * TT) + rg] = mx;
            g_pl[jh * (BB * TT) + rg] = sum;
        }
        #pragma unroll
        for (int q = 0; q < 8; q++) {
            float p = sv[q];
            float pr = __shfl_xor_sync(0xffffffffu, p, 1);
            if (!(lane & 1)) {
                u32 ph = h2pk(p, pr);
                float2 bk = h2f2(ph);
                u32 pl = h2pk(p - bk.x, pr - bk.y);
                int jp = q * 16 + (lane >> 1);
                sph[rrow * PSTR + jp] = ph;
                spl[rrow * PSTR + jp] = pl;
            }
        }
    }
    __syncthreads();

    // phase 2: partial O = P V over this j-half; warp w covers d [w*16, +16)
    float acco[2][4] = {};
    {
        const u32* vbase = g_vt2 + ((size_t)(b * 32 + jh * 16) * 256 + (size_t)(w * 16 + gid)) * 8 + tig * 2;
        #pragma unroll 4
        for (int ks = 0; ks < 16; ks++) {
            int c0 = ks * 8 + tig;
            u32 a0h = sph[gid * PSTR + c0],       a1h = sph[(gid + 8) * PSTR + c0];
            u32 a2h = sph[gid * PSTR + c0 + 4],   a3h = sph[(gid + 8) * PSTR + c0 + 4];
            u32 a0l = spl[gid * PSTR + c0],       a1l = spl[(gid + 8) * PSTR + c0];
            u32 a2l = spl[gid * PSTR + c0 + 4],   a3l = spl[(gid + 8) * PSTR + c0 + 4];
            #pragma unroll
            for (int nt = 0; nt < 2; nt++) {
                uint2 B = *(const uint2*)(vbase + ((size_t)ks * 256 + nt * 8) * 8);
                mma16816h(acco[nt][0],acco[nt][1],acco[nt][2],acco[nt][3],
                          a0h, a1h, a2h, a3h, B.x, B.y);
                mma16816h(acco[nt][0],acco[nt][1],acco[nt][2],acco[nt][3],
                          a0l, a1l, a2l, a3l, B.x, B.y);
            }
        }
    }
    float* po = g_po + (size_t)jh * (BB * TT * CC);
    #pragma unroll
    for (int nt = 0; nt < 2; nt++) {
        int col = w * 16 + nt * 8 + 2 * tig;
        *(float2*)&po[(size_t)(b * TT + i0 + gid) * CC + col]     = make_float2(acco[nt][0], acco[nt][1]);
        *(float2*)&po[(size_t)(b * TT + i0 + gid + 8) * CC + col] = make_float2(acco[nt][2], acco[nt][3]);
    }
}

// ---------------- combine two j-halves ----------------
__global__ __launch_bounds__(256) void combine_kernel(float* __restrict__ out)
{
    int row = blockIdx.x;
    int c = threadIdx.x;
    float mx0 = g_pm[row], mx1 = g_pm[BB * TT + row];
    float l0 = g_pl[row], l1 = g_pl[BB * TT + row];
    float m = fmaxf(mx0, mx1);
    float w0 = __expf(mx0 - m), w1 = __expf(mx1 - m);
    float inv = 1.f / (l0 * w0 + l1 * w1);
    float p0 = g_po[(size_t)row * CC + c];
    float p1 = g_po[(size_t)(BB * TT + row) * CC + c];
    out[(size_t)row * CC + c] = (p0 * w0 + p1 * w1) * inv;
}

// ---------------- launch ----------------
extern "C" void kernel_launch(void* const* d_in, const int* in_sizes, int n_in,
                              void* d_out, int out_size)
{
    (void)in_sizes; (void)n_in; (void)out_size;
    const float* x    = (const float*)d_in[0];
    const float* r    = (const float*)d_in[1];
    const float* w1   = (const float*)d_in[2];
    const float* b1   = (const float*)d_in[3];
    const float* g1   = (const float*)d_in[4];
    const float* be1  = (const float*)d_in[5];
    const float* m1   = (const float*)d_in[6];
    const float* v1   = (const float*)d_in[7];
    const float* w2   = (const float*)d_in[8];
    const float* b2   = (const float*)d_in[9];
    const float* g2   = (const float*)d_in[10];
    const float* be2  = (const float*)d_in[11];
    const float* m2   = (const float*)d_in[12];
    const float* v2   = (const float*)d_in[13];
    const float* wqkv = (const float*)d_in[14];
    float* out = (float*)d_out;

    cudaFuncSetAttribute(bias_kernel, cudaFuncAttributeMaxDynamicSharedMemorySize, BIAS_SMEM);
    cudaFuncSetAttribute(attn_kernel, cudaFuncAttributeMaxDynamicSharedMemorySize, ATT_SMEM);

    prep_kernel<<<193, 256>>>(w1, b1, g1, be1, m1, v1, w2, b2, g2, be2, m2, v2, wqkv);
    bias_kernel<<<BB * TT, 256, BIAS_SMEM>>>(x, r);
    qkv_mma_kernel<<<dim3(24, 16), 256>>>();
    attn_kernel<<<BB * 64, 512, ATT_SMEM>>>();
    combine_kernel<<<BB * TT, 256>>>(out);
}

// round 16
// speedup vs baseline: 1.0812x; 1.0154x over previous
#include <cuda_runtime.h>
#include <cuda_fp16.h>
#include <cstdint>
#include <cstddef>

typedef unsigned long long u64;
typedef unsigned int u32;

#define TT    512
#define BB    2
#define CC    256
#define TPR   12
#define HID   32
#define INNER 256
#define NQKV  768
#define BN_EPS 1e-5f
#define SCALE  0.0625f

// ---------------- scratch (no allocs allowed) ----------------
__device__ __align__(16) u64   g_w1p[16 * TPR];
__device__ __align__(16) u64   g_b1p[16];
__device__ __align__(16) u32   g_w2ph[16 * CC];
__device__ __align__(16) float g_b2f[CC];
__device__ __align__(16) u32   g_xbh[BB * TT * 128];
__device__ __align__(16) u32   g_xbl[BB * TT * 128];
__device__ __align__(16) u32   g_wq2[NQKV * 16 * 16];
__device__ __align__(16) u32   g_q2[BB * TT * 256];
__device__ __align__(16) u32   g_k2[BB * TT * 128];
__device__ __align__(16) u32   g_vt2[BB * 32 * 256 * 8];
// bias j-split partial maxes: [jh(2)][row(1024)][c(256)]
__device__ __align__(16) float g_bmax[2 * BB * TT * CC];
// attn flash-split partials
__device__ __align__(16) float g_po[2 * BB * TT * CC];
__device__ float g_pm[2 * BB * TT];
__device__ float g_pl[2 * BB * TT];

// ---------------- helpers ----------------
__device__ __forceinline__ u64 pk2(float x, float y) {
    u64 r; asm("mov.b64 %0, {%1,%2};" : "=l"(r) : "f"(x), "f"(y)); return r;
}
__device__ __forceinline__ void upk2(u64 v, float &x, float &y) {
    asm("mov.b64 {%0,%1}, %2;" : "=f"(x), "=f"(y) : "l"(v));
}
__device__ __forceinline__ u64 fma2(u64 a, u64 b, u64 c) {
    u64 d; asm("fma.rn.f32x2 %0, %1, %2, %3;" : "=l"(d) : "l"(a), "l"(b), "l"(c)); return d;
}
__device__ __forceinline__ u32 h2pk(float lo, float hi) {
    __half2 t = __floats2half2_rn(lo, hi);
    return *(u32*)&t;
}
__device__ __forceinline__ float2 h2f2(u32 w) {
    __half2 t = *(__half2*)&w;
    return __half22float2(t);
}
__device__ __forceinline__ u32 s2u(const void* p) {
    u32 a; asm("{ .reg .u64 t; cvta.to.shared.u64 t, %1; cvt.u32.u64 %0, t; }" : "=r"(a) : "l"(p));
    return a;
}
__device__ __forceinline__ void mma16816h(float &d0, float &d1, float &d2, float &d3,
                                          u32 a0, u32 a1, u32 a2, u32 a3,
                                          u32 b0, u32 b1) {
    asm volatile("mma.sync.aligned.m16n8k16.row.col.f32.f16.f16.f32 "
                 "{%0,%1,%2,%3}, {%4,%5,%6,%7}, {%8,%9}, {%0,%1,%2,%3};"
                 : "+f"(d0), "+f"(d1), "+f"(d2), "+f"(d3)
                 : "r"(a0), "r"(a1), "r"(a2), "r"(a3), "r"(b0), "r"(b1));
}
__device__ __forceinline__ void ldsm4(u32 &r0, u32 &r1, u32 &r2, u32 &r3, u32 addr) {
    asm volatile("ldmatrix.sync.aligned.m8n8.x4.shared.b16 {%0,%1,%2,%3}, [%4];"
                 : "=r"(r0), "=r"(r1), "=r"(r2), "=r"(r3) : "r"(addr));
}

// ---------------- prep: fold (block 192) + w_qkv convert (blocks 0-191) ----------------
__global__ void prep_kernel(const float* __restrict__ w1, const float* __restrict__ b1,
                            const float* __restrict__ g1, const float* __restrict__ be1,
                            const float* __restrict__ m1, const float* __restrict__ v1,
                            const float* __restrict__ w2, const float* __restrict__ b2,
                            const float* __restrict__ g2, const float* __restrict__ be2,
                            const float* __restrict__ m2, const float* __restrict__ v2,
                            const float* __restrict__ wqkv)
{
    if (blockIdx.x < 192) {
        int n = (blockIdx.x % 3) * 256 + threadIdx.x;
        int byy = blockIdx.x / 3;
        int ks = byy >> 2, tig = byy & 3;
        int k0 = (ks * 8 + tig) * 2;
        float w0 = wqkv[(size_t)k0 * NQKV + n];
        float w1v = wqkv[(size_t)(k0 + 1) * NQKV + n];
        float w8 = wqkv[(size_t)(k0 + 8) * NQKV + n];
        float w9 = wqkv[(size_t)(k0 + 9) * NQKV + n];
        u32 bh0 = h2pk(w0, w1v), bh1 = h2pk(w8, w9);
        float2 r0 = h2f2(bh0), r1 = h2f2(bh1);
        u32 bl0 = h2pk(w0 - r0.x, w1v - r0.y);
        u32 bl1 = h2pk(w8 - r1.x, w9 - r1.y);
        *(uint4*)(g_wq2 + ((size_t)(n * 16 + ks) * 4 + tig) * 4) = make_uint4(bh0, bh1, bl0, bl1);
        return;
    }
    __shared__ float a1s[HID], b1s[HID];
    int t = threadIdx.x;
    if (t < HID) {
        float a = g1[t] * rsqrtf(v1[t] + BN_EPS);
        a1s[t] = a;
        b1s[t] = (b1[t] - m1[t]) * a + be1[t];
    }
    __syncthreads();
    if (t < 16) {
        for (int d = 0; d < TPR; d++)
            g_w1p[t * TPR + d] = pk2(w1[d * HID + 2 * t]     * a1s[2 * t],
                                     w1[d * HID + 2 * t + 1] * a1s[2 * t + 1]);
        g_b1p[t] = pk2(b1s[2 * t], b1s[2 * t + 1]);
    }
    int c = t;
    float a2 = g2[c] * rsqrtf(v2[c] + BN_EPS);
    g_b2f[c] = (b2[c] - m2[c]) * a2 + be2[c];
    for (int kp = 0; kp < 16; kp++) {
        float w0  = w2[(2 * kp)     * CC + c] * a2;
        float w1v = w2[(2 * kp + 1) * CC + c] * a2;
        g_w2ph[kp * CC + c] = h2pk(w0, w1v);
    }
}

// ---------------- TPR-MLP: j-split across 2 blocks, hi-only fp16 h1 ----------------
#define H1S 80
#define BIAS_SMEM (256 * H1S + 208 * 8)

__global__ __launch_bounds__(256, 3) void bias_split_kernel(const float* __restrict__ r)
{
    extern __shared__ char smem[];
    char* buf = smem;
    u64*  w1s = (u64*)(smem + 256 * H1S);

    int tid  = threadIdx.x;
    int bi   = blockIdx.x >> 1;
    int jh   = blockIdx.x & 1;
    int warp = tid >> 5, lane = tid & 31;
    int gid  = lane >> 2, tig = lane & 3;

    if (tid < 208) w1s[tid] = (tid < 192) ? g_w1p[tid] : g_b1p[tid - 192];

    u32 bh[4][2][2];
    #pragma unroll
    for (int nt = 0; nt < 4; nt++) {
        int c = warp * 32 + nt * 8 + gid;
        #pragma unroll
        for (int ks = 0; ks < 2; ks++) {
            bh[nt][ks][0] = g_w2ph[(ks * 8 + tig)     * CC + c];
            bh[nt][ks][1] = g_w2ph[(ks * 8 + tig + 4) * CC + c];
        }
    }

    // this thread's r row: j = jh*256 + tid
    const float4* rr = (const float4*)(r + (size_t)bi * (TT * TPR) + (size_t)(jh * 256 + tid) * TPR);
    float4 A0 = rr[0], B0 = rr[1], C0 = rr[2];

    int t4 = lane >> 3;
    u32 laneoff = (u32)(((t4 & 1) * 8 + (lane & 7)) * H1S + (t4 >> 1) * 16);
    u32 h1b = s2u(buf) + laneoff;

    float m0[4], m1[4];
    #pragma unroll
    for (int nt = 0; nt < 4; nt++) { m0[nt] = -3.4e38f; m1[nt] = -3.4e38f; }

    __syncthreads();   // w1s ready

    // layer 1: one row per thread
    {
        u64 rp[12];
        rp[0]=pk2(A0.x,A0.x); rp[1]=pk2(A0.y,A0.y); rp[2]=pk2(A0.z,A0.z); rp[3]=pk2(A0.w,A0.w);
        rp[4]=pk2(B0.x,B0.x); rp[5]=pk2(B0.y,B0.y); rp[6]=pk2(B0.z,B0.z); rp[7]=pk2(B0.w,B0.w);
        rp[8]=pk2(C0.x,C0.x); rp[9]=pk2(C0.y,C0.y); rp[10]=pk2(C0.z,C0.z); rp[11]=pk2(C0.w,C0.w);
        u32* row = (u32*)(buf + tid * H1S);
        #pragma unroll 4
        for (int kp = 0; kp < 16; kp++) {
            u64 acc = w1s[192 + kp];
            #pragma unroll
            for (int d = 0; d < 12; d++) acc = fma2(rp[d], w1s[kp * TPR + d], acc);
            float h0, h1; upk2(acc, h0, h1);
            h0 = fmaxf(h0, 0.f); h1 = fmaxf(h1, 0.f);
            row[kp] = h2pk(h0, h1);
        }
    }
    __syncthreads();

    // layer 2: 16 j-tiles of 16 rows
    #pragma unroll 2
    for (int jt = 0; jt < 16; jt++) {
        u32 a = h1b + (u32)jt * (16 * H1S);
        u32 ah0[4], ah1[4];
        ldsm4(ah0[0],ah0[1],ah0[2],ah0[3], a);
        ldsm4(ah1[0],ah1[1],ah1[2],ah1[3], a + 32);
        #pragma unroll
        for (int nt = 0; nt < 4; nt++) {
            float d0 = 0.f, d1 = 0.f, d2 = 0.f, d3 = 0.f;
            mma16816h(d0,d1,d2,d3, ah0[0],ah0[1],ah0[2],ah0[3], bh[nt][0][0], bh[nt][0][1]);
            mma16816h(d0,d1,d2,d3, ah1[0],ah1[1],ah1[2],ah1[3], bh[nt][1][0], bh[nt][1][1]);
            m0[nt] = fmaxf(m0[nt], fmaxf(d0, d2));
            m1[nt] = fmaxf(m1[nt], fmaxf(d1, d3));
        }
    }

    // reduce max across gid lanes, write partial
    float* bm = g_bmax + (size_t)jh * (BB * TT * CC) + (size_t)bi * CC;
    #pragma unroll
    for (int nt = 0; nt < 4; nt++) {
        #pragma unroll
        for (int o = 4; o < 32; o <<= 1) {
            m0[nt] = fmaxf(m0[nt], __shfl_xor_sync(0xffffffffu, m0[nt], o));
            m1[nt] = fmaxf(m1[nt], __shfl_xor_sync(0xffffffffu, m1[nt], o));
        }
        if (gid == 0) {
            int c0 = warp * 32 + nt * 8 + tig * 2;
            bm[c0]     = m0[nt];
            bm[c0 + 1] = m1[nt];
        }
    }
}

// ---------------- combine bias halves -> xb fragment words ----------------
__global__ __launch_bounds__(128) void bias_combine_kernel(const float* __restrict__ x)
{
    int bi = blockIdx.x;
    int P  = threadIdx.x;          // c-pair index 0..127
    int c0 = P * 2;
    const float* bm0 = g_bmax + (size_t)bi * CC;
    const float* bm1 = g_bmax + (size_t)(BB * TT + bi) * CC;
    float2 a = *(const float2*)(bm0 + c0);
    float2 b = *(const float2*)(bm1 + c0);
    float mz0 = fmaxf(a.x, b.x), mz1 = fmaxf(a.y, b.y);
    float v0 = x[(size_t)bi * CC + c0]     + fmaxf(mz0 + g_b2f[c0],     0.f);
    float v1 = x[(size_t)bi * CC + c0 + 1] + fmaxf(mz1 + g_b2f[c0 + 1], 0.f);
    int word = (P & ~7) + ((P & 3) << 1) + ((P >> 2) & 1);
    u32 hi = h2pk(v0, v1);
    float2 bk = h2f2(hi);
    g_xbh[bi * 128 + word] = hi;
    g_xbl[bi * 128 + word] = h2pk(v0 - bk.x, v1 - bk.y);
}

// ---------------- qkv via fp16 MMA (3-term), n-tile 32, k-split ----------
__global__ __launch_bounds__(256) void qkv_mma_kernel()
{
    __shared__ float sacc[4][4][32][4];
    int tid = threadIdx.x;
    int warp = tid >> 5, lane = tid & 31, gid = lane >> 2, tig = lane & 3;
    int rt = warp & 3, kh = warp >> 2;
    int r0 = blockIdx.y * 64 + rt * 16;
    int n0 = blockIdx.x * 32;
    int type = blockIdx.x >> 3;

    const u32* ah = g_xbh + (size_t)(r0 + gid) * 128 + kh * 64 + tig * 2;
    const u32* al = g_xbl + (size_t)(r0 + gid) * 128 + kh * 64 + tig * 2;

    float acc[4][4] = {};
    #pragma unroll 4
    for (int ks = 0; ks < 8; ks++) {
        uint2 Ah0 = *(const uint2*)(ah + ks * 8);
        uint2 Ah1 = *(const uint2*)(ah + 8 * 128 + ks * 8);
        uint2 Al0 = *(const uint2*)(al + ks * 8);
        uint2 Al1 = *(const uint2*)(al + 8 * 128 + ks * 8);
        #pragma unroll
        for (int nt = 0; nt < 4; nt++) {
            int n = n0 + nt * 8 + gid;
            uint4 B = *(const uint4*)(g_wq2 + ((size_t)(n * 16 + kh * 8 + ks) * 4 + tig) * 4);
            mma16816h(acc[nt][0],acc[nt][1],acc[nt][2],acc[nt][3],
                      Ah0.x, Ah1.x, Ah0.y, Ah1.y, B.x, B.y);
            mma16816h(acc[nt][0],acc[nt][1],acc[nt][2],acc[nt][3],
                      Ah0.x, Ah1.x, Ah0.y, Ah1.y, B.z, B.w);
            mma16816h(acc[nt][0],acc[nt][1],acc[nt][2],acc[nt][3],
                      Al0.x, Al1.x, Al0.y, Al1.y, B.x, B.y);
        }
    }

    if (kh == 0) {
        #pragma unroll
        for (int nt = 0; nt < 4; nt++)
            *(float4*)&sacc[rt][nt][lane][0] = make_float4(acc[nt][0], acc[nt][1], acc[nt][2], acc[nt][3]);
    }
    __syncthreads();
    if (kh == 0) return;

    #pragma unroll
    for (int nt = 0; nt < 4; nt++) {
        float4 t = *(float4*)&sacc[rt][nt][lane][0];
        acc[nt][0] += t.x; acc[nt][1] += t.y; acc[nt][2] += t.z; acc[nt][3] += t.w;
    }

    if (type == 0) {
        #pragma unroll
        for (int nt = 0; nt < 4; nt++) {
            int P = (n0 >> 1) + nt * 4 + tig;
            int word = ((P >> 3) << 4) + ((P & 3) << 2) + ((P >> 2) & 1);
            u32* q0 = g_q2 + (size_t)(r0 + gid) * 256 + word;
            u32* q1 = g_q2 + (size_t)(r0 + gid + 8) * 256 + word;
            u32 h0 = h2pk(acc[nt][0], acc[nt][1]); float2 b0 = h2f2(h0);
            u32 h1 = h2pk(acc[nt][2], acc[nt][3]); float2 b1 = h2f2(h1);
            q0[0] = h0; q0[2] = h2pk(acc[nt][0] - b0.x, acc[nt][1] - b0.y);
            q1[0] = h1; q1[2] = h2pk(acc[nt][2] - b1.x, acc[nt][3] - b1.y);
        }
    } else if (type == 1) {
        #pragma unroll
        for (int nt = 0; nt < 4; nt++) {
            int P = ((n0 - 256) >> 1) + nt * 4 + tig;
            int word = (P & ~7) + ((P & 3) << 1) + ((P >> 2) & 1);
            g_k2[(size_t)(r0 + gid) * 128 + word]     = h2pk(acc[nt][0], acc[nt][1]);
            g_k2[(size_t)(r0 + gid + 8) * 128 + word] = h2pk(acc[nt][2], acc[nt][3]);
        }
    } else {
        int bb = r0 >> 9, ksj = (r0 & 511) >> 4;
        #pragma unroll
        for (int nt = 0; nt < 4; nt++) {
            float p0 = __shfl_xor_sync(0xffffffffu, acc[nt][0], 4);
            float p1 = __shfl_xor_sync(0xffffffffu, acc[nt][1], 4);
            float p2 = __shfl_xor_sync(0xffffffffu, acc[nt][2], 4);
            float p3 = __shfl_xor_sync(0xffffffffu, acc[nt][3], 4);
            if (!(gid & 1)) {
                int tigj = gid >> 1;
                int d0c = n0 - 512 + nt * 8 + 2 * tig;
                u32* v0p = g_vt2 + ((size_t)(bb * 32 + ksj) * 256 + d0c) * 8 + tigj * 2;
                v0p[0] = h2pk(acc[nt][0], p0);
                v0p[1] = h2pk(acc[nt][2], p2);
                u32* v1p = v0p + 8;
                v1p[0] = h2pk(acc[nt][1], p1);
                v1p[1] = h2pk(acc[nt][3], p3);
            }
        }
    }
}

// ---------------- flash-split attention: j-halves across 2 blocks ----------------
#define QSTR 260
#define SSTR 260
#define PSTR 132
#define ATT_SMEM (16*QSTR*4 + 16*SSTR*4 + 2*16*PSTR*4)

__global__ __launch_bounds__(512, 1) void attn_kernel()
{
    extern __shared__ char smem[];
    u32*   sq  = (u32*)smem;
    float* ssc = (float*)(smem + 16 * QSTR * 4);
    u32*   sph = (u32*)(smem + 16 * QSTR * 4 + 16 * SSTR * 4);
    u32*   spl = sph + 16 * PSTR;

    int tid = threadIdx.x;
    int w = tid >> 5, lane = tid & 31, gid = lane >> 2, tig = lane & 3;
    int b  = blockIdx.x >> 6;
    int it = (blockIdx.x >> 1) & 31;
    int jh = blockIdx.x & 1;
    int i0 = it * 16;

    {
        int i = tid >> 5, c0 = (tid & 31) * 8;
        const uint4* src = (const uint4*)(g_q2 + (size_t)(b * TT + i0 + i) * 256 + c0);
        uint4* dst = (uint4*)(sq + i * QSTR + c0);
        dst[0] = src[0]; dst[1] = src[1];
    }
    __syncthreads();

    float accs[2][4] = {};
    {
        const u32* qr0 = sq + gid * QSTR;
        const u32* qr1 = sq + (gid + 8) * QSTR;
        const u32* kbase = g_k2 + (size_t)(b * TT + jh * 256 + w * 16 + gid) * 128 + tig * 2;
        #pragma unroll 4
        for (int ks = 0; ks < 16; ks++) {
            uint4 A0 = *(const uint4*)(qr0 + ks * 16 + tig * 4);
            uint4 A1 = *(const uint4*)(qr1 + ks * 16 + tig * 4);
            #pragma unroll
            for (int nt = 0; nt < 2; nt++) {
                uint2 B = *(const uint2*)(kbase + (size_t)nt * 8 * 128 + ks * 8);
                mma16816h(accs[nt][0],accs[nt][1],accs[nt][2],accs[nt][3],
                          A0.x, A1.x, A0.y, A1.y, B.x, B.y);
                mma16816h(accs[nt][0],accs[nt][1],accs[nt][2],accs[nt][3],
                          A0.z, A1.z, A0.w, A1.w, B.x, B.y);
            }
        }
        #pragma unroll
        for (int nt = 0; nt < 2; nt++) {
            int col = w * 16 + nt * 8 + 2 * tig;
            *(float2*)&ssc[gid * SSTR + col]       = make_float2(accs[nt][0] * SCALE, accs[nt][1] * SCALE);
            *(float2*)&ssc[(gid + 8) * SSTR + col] = make_float2(accs[nt][2] * SCALE, accs[nt][3] * SCALE);
        }
    }
    __syncthreads();

    {
        int rrow = w;
        float sv[8];
        float mx = -3.4e38f;
        #pragma unroll
        for (int q = 0; q < 8; q++) {
            sv[q] = ssc[rrow * SSTR + q * 32 + lane];
            mx = fmaxf(mx, sv[q]);
        }
        #pragma unroll
        for (int o = 16; o; o >>= 1) mx = fmaxf(mx, __shfl_xor_sync(0xffffffffu, mx, o));
        float sum = 0.f;
        #pragma unroll
        for (int q = 0; q < 8; q++) { sv[q] = __expf(sv[q] - mx); sum += sv[q]; }
        #pragma unroll
        for (int o = 16; o; o >>= 1) sum += __shfl_xor_sync(0xffffffffu, sum, o);
        if (lane == 0) {
            int rg = b * TT + i0 + rrow;
            g_pm[jh * (BB * TT) + rg] = mx;
            g_pl[jh * (BB * TT) + rg] = sum;
        }
        #pragma unroll
        for (int q = 0; q < 8; q++) {
            float p = sv[q];
            float pr = __shfl_xor_sync(0xffffffffu, p, 1);
            if (!(lane & 1)) {
                u32 ph = h2pk(p, pr);
                float2 bk = h2f2(ph);
                u32 pl = h2pk(p - bk.x, pr - bk.y);
                int jp = q * 16 + (lane >> 1);
                sph[rrow * PSTR + jp] = ph;
                spl[rrow * PSTR + jp] = pl;
            }
        }
    }
    __syncthreads();

    float acco[2][4] = {};
    {
        const u32* vbase = g_vt2 + ((size_t)(b * 32 + jh * 16) * 256 + (size_t)(w * 16 + gid)) * 8 + tig * 2;
        #pragma unroll 4
        for (int ks = 0; ks < 16; ks++) {
            int c0 = ks * 8 + tig;
            u32 a0h = sph[gid * PSTR + c0],       a1h = sph[(gid + 8) * PSTR + c0];
            u32 a2h = sph[gid * PSTR + c0 + 4],   a3h = sph[(gid + 8) * PSTR + c0 + 4];
            u32 a0l = spl[gid * PSTR + c0],       a1l = spl[(gid + 8) * PSTR + c0];
            u32 a2l = spl[gid * PSTR + c0 + 4],   a3l = spl[(gid + 8) * PSTR + c0 + 4];
            #pragma unroll
            for (int nt = 0; nt < 2; nt++) {
                uint2 B = *(const uint2*)(vbase + ((size_t)ks * 256 + nt * 8) * 8);
                mma16816h(acco[nt][0],acco[nt][1],acco[nt][2],acco[nt][3],
                          a0h, a1h, a2h, a3h, B.x, B.y);
                mma16816h(acco[nt][0],acco[nt][1],acco[nt][2],acco[nt][3],
                          a0l, a1l, a2l, a3l, B.x, B.y);
            }
        }
    }
    float* po = g_po + (size_t)jh * (BB * TT * CC);
    #pragma unroll
    for (int nt = 0; nt < 2; nt++) {
        int col = w * 16 + nt * 8 + 2 * tig;
        *(float2*)&po[(size_t)(b * TT + i0 + gid) * CC + col]     = make_float2(acco[nt][0], acco[nt][1]);
        *(float2*)&po[(size_t)(b * TT + i0 + gid + 8) * CC + col] = make_float2(acco[nt][2], acco[nt][3]);
    }
}

// ---------------- combine two attention j-halves ----------------
__global__ __launch_bounds__(256) void combine_kernel(float* __restrict__ out)
{
    int row = blockIdx.x;
    int c = threadIdx.x;
    float mx0 = g_pm[row], mx1 = g_pm[BB * TT + row];
    float l0 = g_pl[row], l1 = g_pl[BB * TT + row];
    float m = fmaxf(mx0, mx1);
    float w0 = __expf(mx0 - m), w1 = __expf(mx1 - m);
    float inv = 1.f / (l0 * w0 + l1 * w1);
    float p0 = g_po[(size_t)row * CC + c];
    float p1 = g_po[(size_t)(BB * TT + row) * CC + c];
    out[(size_t)row * CC + c] = (p0 * w0 + p1 * w1) * inv;
}

// ---------------- launch ----------------
extern "C" void kernel_launch(void* const* d_in, const int* in_sizes, int n_in,
                              void* d_out, int out_size)
{
    (void)in_sizes; (void)n_in; (void)out_size;
    const float* x    = (const float*)d_in[0];
    const float* r    = (const float*)d_in[1];
    const float* w1   = (const float*)d_in[2];
    const float* b1   = (const float*)d_in[3];
    const float* g1   = (const float*)d_in[4];
    const float* be1  = (const float*)d_in[5];
    const float* m1   = (const float*)d_in[6];
    const float* v1   = (const float*)d_in[7];
    const float* w2   = (const float*)d_in[8];
    const float* b2   = (const float*)d_in[9];
    const float* g2   = (const float*)d_in[10];
    const float* be2  = (const float*)d_in[11];
    const float* m2   = (const float*)d_in[12];
    const float* v2   = (const float*)d_in[13];
    const float* wqkv = (const float*)d_in[14];
    float* out = (float*)d_out;

    cudaFuncSetAttribute(bias_split_kernel, cudaFuncAttributeMaxDynamicSharedMemorySize, BIAS_SMEM);
    cudaFuncSetAttribute(attn_kernel, cudaFuncAttributeMaxDynamicSharedMemorySize, ATT_SMEM);

    prep_kernel<<<193, 256>>>(w1, b1, g1, be1, m1, v1, w2, b2, g2, be2, m2, v2, wqkv);
    bias_split_kernel<<<BB * TT * 2, 256, BIAS_SMEM>>>(r);
    bias_combine_kernel<<<BB * TT, 128>>>(x);
    qkv_mma_kernel<<<dim3(24, 16), 256>>>();
    attn_kernel<<<BB * 64, 512, ATT_SMEM>>>();
    combine_kernel<<<BB * TT, 256>>>(out);
}